// round 7
// baseline (speedup 1.0000x reference)
#include <cuda_runtime.h>
#include <math.h>

// Problem constants
#define BB   2
#define NN   8192
#define CC   512
#define HH   8
#define DD   64
#define MM   (BB*NN)      // 16384 rows
#define K3C  (3*CC)       // 1536
#define LCH  64           // chunk length
#define NCH  (NN/LCH)     // 128 chunks per (b,h)
#define BHH  (BB*HH)      // 16

// Scratch (device globals; no allocation allowed)
__device__ float g_q[BHH*NN*DD];
__device__ float g_k[BHH*NN*DD];
__device__ float g_v[BHH*NN*DD];
__device__ float g_S[BHH*NCH*DD*DD];   // per-chunk KV outer products -> exclusive prefix
__device__ float g_attn[BB*NN*CC];

__device__ __forceinline__ float feat(float x) {
    // elu(x)+1 = x+1 (x>0) else exp(x)
    return x > 0.f ? x + 1.f : __expf(x);
}

// ---------------------------------------------------------------------------
// Fused NT GEMM: Y = A[M,512] @ W[N,512]^T, tile 128x128x16, 256 threads,
// 8x8 micro-tile, double-buffered smem, A stored k-major in smem.
// Branch-free mainloop with peeled last tile. Vectorized (STG.128) epilogue.
// MODE 0: A = X (param), epilogue scatters to g_q/g_k/g_v with feature map.
// MODE 1: A = g_attn (device global), epilogue adds bias, writes out.
// ---------------------------------------------------------------------------
template <int MODE>
__global__ __launch_bounds__(256) void gemm_nt_kernel(const float* __restrict__ X,
                                                      const float* __restrict__ W,
                                                      const float* __restrict__ bias,
                                                      float* __restrict__ out) {
    __shared__ float As[2][16][128];
    __shared__ float Bs[2][16][128];

    const float* Abase = (MODE == 0) ? X : (const float*)g_attn;

    const int m0 = blockIdx.x * 128;
    const int n0 = blockIdx.y * 128;
    const int tid = threadIdx.x;
    const int tx = tid & 15;          // 0..15 -> col groups
    const int ty = tid >> 4;          // 0..15 -> row groups
    const int lr = tid >> 2;          // 0..63 load row
    const int lc = (tid & 3) << 2;    // 0,4,8,12 load col (k)

    const float* Arow0 = Abase + (size_t)(m0 + lr) * CC + lc;
    const float* Arow1 = Abase + (size_t)(m0 + lr + 64) * CC + lc;
    const float* Brow0 = W + (size_t)(n0 + lr) * CC + lc;
    const float* Brow1 = W + (size_t)(n0 + lr + 64) * CC + lc;

    float acc[8][8];
    #pragma unroll
    for (int i = 0; i < 8; i++)
        #pragma unroll
        for (int j = 0; j < 8; j++) acc[i][j] = 0.f;

    // Stage tile 0
    {
        float4 a0 = *reinterpret_cast<const float4*>(Arow0);
        float4 a1 = *reinterpret_cast<const float4*>(Arow1);
        float4 b0 = *reinterpret_cast<const float4*>(Brow0);
        float4 b1 = *reinterpret_cast<const float4*>(Brow1);
        As[0][lc+0][lr] = a0.x; As[0][lc+1][lr] = a0.y; As[0][lc+2][lr] = a0.z; As[0][lc+3][lr] = a0.w;
        As[0][lc+0][lr+64] = a1.x; As[0][lc+1][lr+64] = a1.y; As[0][lc+2][lr+64] = a1.z; As[0][lc+3][lr+64] = a1.w;
        Bs[0][lc+0][lr] = b0.x; Bs[0][lc+1][lr] = b0.y; Bs[0][lc+2][lr] = b0.z; Bs[0][lc+3][lr] = b0.w;
        Bs[0][lc+0][lr+64] = b1.x; Bs[0][lc+1][lr+64] = b1.y; Bs[0][lc+2][lr+64] = b1.z; Bs[0][lc+3][lr+64] = b1.w;
    }
    __syncthreads();

    const int KT = CC / 16;   // 32

    // Branch-free steady state: iterations 0 .. KT-2, each prefetches kt+1.
    #pragma unroll 1
    for (int kt = 0; kt < KT - 1; kt++) {
        const int off = (kt + 1) * 16;
        float4 a0 = *reinterpret_cast<const float4*>(Arow0 + off);
        float4 a1 = *reinterpret_cast<const float4*>(Arow1 + off);
        float4 b0 = *reinterpret_cast<const float4*>(Brow0 + off);
        float4 b1 = *reinterpret_cast<const float4*>(Brow1 + off);

        const int cur = kt & 1;
        #pragma unroll
        for (int kk = 0; kk < 16; kk++) {
            float4 af0 = *reinterpret_cast<const float4*>(&As[cur][kk][ty * 4]);
            float4 af1 = *reinterpret_cast<const float4*>(&As[cur][kk][ty * 4 + 64]);
            float4 bf0 = *reinterpret_cast<const float4*>(&Bs[cur][kk][tx * 4]);
            float4 bf1 = *reinterpret_cast<const float4*>(&Bs[cur][kk][tx * 4 + 64]);
            float a[8] = {af0.x, af0.y, af0.z, af0.w, af1.x, af1.y, af1.z, af1.w};
            float b[8] = {bf0.x, bf0.y, bf0.z, bf0.w, bf1.x, bf1.y, bf1.z, bf1.w};
            #pragma unroll
            for (int i = 0; i < 8; i++)
                #pragma unroll
                for (int j = 0; j < 8; j++) acc[i][j] = fmaf(a[i], b[j], acc[i][j]);
        }
        const int nxt = cur ^ 1;
        As[nxt][lc+0][lr] = a0.x; As[nxt][lc+1][lr] = a0.y; As[nxt][lc+2][lr] = a0.z; As[nxt][lc+3][lr] = a0.w;
        As[nxt][lc+0][lr+64] = a1.x; As[nxt][lc+1][lr+64] = a1.y; As[nxt][lc+2][lr+64] = a1.z; As[nxt][lc+3][lr+64] = a1.w;
        Bs[nxt][lc+0][lr] = b0.x; Bs[nxt][lc+1][lr] = b0.y; Bs[nxt][lc+2][lr] = b0.z; Bs[nxt][lc+3][lr] = b0.w;
        Bs[nxt][lc+0][lr+64] = b1.x; Bs[nxt][lc+1][lr+64] = b1.y; Bs[nxt][lc+2][lr+64] = b1.z; Bs[nxt][lc+3][lr+64] = b1.w;
        __syncthreads();
    }

    // Peeled last tile: compute only.
    {
        const int cur = (KT - 1) & 1;
        #pragma unroll
        for (int kk = 0; kk < 16; kk++) {
            float4 af0 = *reinterpret_cast<const float4*>(&As[cur][kk][ty * 4]);
            float4 af1 = *reinterpret_cast<const float4*>(&As[cur][kk][ty * 4 + 64]);
            float4 bf0 = *reinterpret_cast<const float4*>(&Bs[cur][kk][tx * 4]);
            float4 bf1 = *reinterpret_cast<const float4*>(&Bs[cur][kk][tx * 4 + 64]);
            float a[8] = {af0.x, af0.y, af0.z, af0.w, af1.x, af1.y, af1.z, af1.w};
            float b[8] = {bf0.x, bf0.y, bf0.z, bf0.w, bf1.x, bf1.y, bf1.z, bf1.w};
            #pragma unroll
            for (int i = 0; i < 8; i++)
                #pragma unroll
                for (int j = 0; j < 8; j++) acc[i][j] = fmaf(a[i], b[j], acc[i][j]);
        }
    }

    // Vectorized epilogue: each j-group of 4 is 4 consecutive n.
    if (MODE == 1) {
        const float4 bias0 = *reinterpret_cast<const float4*>(&bias[n0 + tx * 4]);
        const float4 bias1 = *reinterpret_cast<const float4*>(&bias[n0 + tx * 4 + 64]);
        #pragma unroll
        for (int i = 0; i < 8; i++) {
            const int m = m0 + ty * 4 + (i & 3) + (i >> 2) * 64;
            float4 o0 = {acc[i][0] + bias0.x, acc[i][1] + bias0.y,
                         acc[i][2] + bias0.z, acc[i][3] + bias0.w};
            float4 o1 = {acc[i][4] + bias1.x, acc[i][5] + bias1.y,
                         acc[i][6] + bias1.z, acc[i][7] + bias1.w};
            *reinterpret_cast<float4*>(&out[(size_t)m * CC + n0 + tx * 4]) = o0;
            *reinterpret_cast<float4*>(&out[(size_t)m * CC + n0 + tx * 4 + 64]) = o1;
        }
    } else {
        #pragma unroll
        for (int i = 0; i < 8; i++) {
            const int m = m0 + ty * 4 + (i & 3) + (i >> 2) * 64;
            const int b = m >> 13;
            const int t = m & (NN - 1);
            #pragma unroll
            for (int jg = 0; jg < 2; jg++) {
                const int n = n0 + tx * 4 + jg * 64;   // 4 consecutive n from here
                const int sec = n >> 9;                // 0=q,1=k,2=v (same for all 4)
                const int h = (n >> 6) & 7;
                const int d = n & 63;                  // d..d+3 within one head
                float v0 = acc[i][jg * 4 + 0];
                float v1 = acc[i][jg * 4 + 1];
                float v2 = acc[i][jg * 4 + 2];
                float v3 = acc[i][jg * 4 + 3];
                if (sec < 2) { v0 = feat(v0); v1 = feat(v1); v2 = feat(v2); v3 = feat(v3); }
                float* dst = (sec == 0) ? g_q : ((sec == 1) ? g_k : g_v);
                float4 o = {v0, v1, v2, v3};
                *reinterpret_cast<float4*>(
                    &dst[(((size_t)(b * HH + h)) * NN + t) * DD + d]) = o;
            }
        }
    }
}

// ---------------------------------------------------------------------------
// Kernel 2: per-chunk S_c = k_c^T v_c  (D x D), 2048 blocks of 256 threads.
// float4 smem fragments: 2 LDS.128 per 16 FMA.
// ---------------------------------------------------------------------------
__global__ __launch_bounds__(256) void chunk_kv_kernel() {
    const int bh = blockIdx.x >> 7;     // NCH=128
    const int c  = blockIdx.x & (NCH - 1);
    __shared__ float Ks[LCH * DD];
    __shared__ float Vs[LCH * DD];
    const size_t cb = ((size_t)bh * NN + (size_t)c * LCH) * DD;
    const int tid = threadIdx.x;
    for (int i = tid * 4; i < LCH * DD; i += 1024) {
        *reinterpret_cast<float4*>(&Ks[i]) = *reinterpret_cast<const float4*>(&g_k[cb + i]);
        *reinterpret_cast<float4*>(&Vs[i]) = *reinterpret_cast<const float4*>(&g_v[cb + i]);
    }
    __syncthreads();
    const int tx = tid & 15, ty = tid >> 4;
    float acc[4][4];
    #pragma unroll
    for (int i = 0; i < 4; i++)
        #pragma unroll
        for (int j = 0; j < 4; j++) acc[i][j] = 0.f;
    for (int t = 0; t < LCH; t++) {
        float4 a4 = *reinterpret_cast<const float4*>(&Ks[t * DD + ty * 4]);
        float4 b4 = *reinterpret_cast<const float4*>(&Vs[t * DD + tx * 4]);
        float a[4] = {a4.x, a4.y, a4.z, a4.w};
        float b[4] = {b4.x, b4.y, b4.z, b4.w};
        #pragma unroll
        for (int i = 0; i < 4; i++)
            #pragma unroll
            for (int j = 0; j < 4; j++) acc[i][j] = fmaf(a[i], b[j], acc[i][j]);
    }
    float* Sb = g_S + (size_t)blockIdx.x * (DD * DD);
    #pragma unroll
    for (int i = 0; i < 4; i++) {
        float4 o = {acc[i][0], acc[i][1], acc[i][2], acc[i][3]};
        *reinterpret_cast<float4*>(&Sb[(ty * 4 + i) * DD + tx * 4]) = o;
    }
}

// ---------------------------------------------------------------------------
// Kernel 3: exclusive prefix sum of S over chunks, per (b,h).
// One thread per independent (bh, element) sequence: 65536 threads,
// 256 blocks -> whole chip active, fully coalesced, MLP-pipelined.
// ---------------------------------------------------------------------------
__global__ __launch_bounds__(256) void scan_kernel() {
    const int g = blockIdx.x * 256 + threadIdx.x;   // 0 .. 65535
    const int bh = g >> 12;                          // 0..15
    const int elem = g & 4095;                       // 0..4095
    float* p = g_S + (size_t)bh * NCH * (DD * DD) + elem;
    float run = 0.f;
    #pragma unroll 8
    for (int c = 0; c < NCH; c++) {
        const float s = p[(size_t)c * (DD * DD)];
        p[(size_t)c * (DD * DD)] = run;              // exclusive prefix in-place
        run += s;
    }
}

// ---------------------------------------------------------------------------
// Kernel 4: per chunk  out = tril(q k^T) v + q @ KV_prev.
// XOR-swizzled smem (stride 64, conflict-free) — 48KB static smem.
// V load hoisted before matmul 1; KV-prefix prefetched into registers
// during the A@V loop (both latency-overlapped with compute).
// ---------------------------------------------------------------------------
#define SW(r, c) (((r) << 6) | ((c) ^ ((r) & 31)))

__global__ __launch_bounds__(256) void attn_chunk_kernel() {
    const int bh = blockIdx.x >> 7;
    const int c  = blockIdx.x & (NCH - 1);
    __shared__ float QT[LCH * DD];   // swizzled, transposed [d][t]
    __shared__ float B1[LCH * DD];   // K^T (swizzled) then A (swizzled)
    __shared__ float B2[LCH * DD];   // V (plain) then KV (plain)
    const size_t cb = ((size_t)bh * NN + (size_t)c * LCH) * DD;
    const int tid = threadIdx.x;
    const int tx = tid & 15, ty = tid >> 4;

    // Hoisted V load: B2 is not read until after the 2nd barrier, so fill it
    // now and let the gmem latency overlap with matmul 1.
    for (int i = tid * 4; i < LCH * DD; i += 1024)
        *reinterpret_cast<float4*>(&B2[i]) = *reinterpret_cast<const float4*>(&g_v[cb + i]);

    // Load q,k transposed+swizzled: gmem coalesced, smem conflict-free.
    for (int i = tid; i < LCH * DD; i += 256) {
        const int t = i >> 6, d = i & 63;
        const float qv = g_q[cb + i];
        const float kv = g_k[cb + i];
        QT[SW(d, t)] = qv;
        B1[SW(d, t)] = kv;
    }
    __syncthreads();

    // A[t][s] = sum_d q[t][d] k[s][d]
    float A[4][4];
    #pragma unroll
    for (int i = 0; i < 4; i++)
        #pragma unroll
        for (int j = 0; j < 4; j++) A[i][j] = 0.f;
    for (int kk = 0; kk < DD; kk++) {
        float a[4], b[4];
        #pragma unroll
        for (int i = 0; i < 4; i++) a[i] = QT[SW(kk, ty * 4 + i)];
        #pragma unroll
        for (int j = 0; j < 4; j++) b[j] = B1[SW(kk, tx * 4 + j)];
        #pragma unroll
        for (int i = 0; i < 4; i++)
            #pragma unroll
            for (int j = 0; j < 4; j++) A[i][j] = fmaf(a[i], b[j], A[i][j]);
    }
    __syncthreads();

    // Write masked A into B1 (K dead). V already resident in B2.
    #pragma unroll
    for (int i = 0; i < 4; i++) {
        const int t = ty * 4 + i;
        #pragma unroll
        for (int j = 0; j < 4; j++) {
            const int s = tx * 4 + j;
            B1[SW(t, s)] = (s <= t) ? A[i][j] : 0.f;   // causal, inclusive
        }
    }
    __syncthreads();

    // Prefetch the exclusive-prefix KV tile into registers; consumed after
    // the A@V loop (latency hidden behind 64 FMA iterations).
    float4 kvp[4];
    {
        const float* Sb = g_S + (size_t)blockIdx.x * (DD * DD);
        #pragma unroll
        for (int r = 0; r < 4; r++)
            kvp[r] = *reinterpret_cast<const float4*>(&Sb[tid * 4 + r * 1024]);
    }

    // out = A @ V
    float out[4][4];
    #pragma unroll
    for (int i = 0; i < 4; i++)
        #pragma unroll
        for (int j = 0; j < 4; j++) out[i][j] = 0.f;
    for (int kk = 0; kk < LCH; kk++) {
        float a[4];
        #pragma unroll
        for (int i = 0; i < 4; i++) a[i] = B1[SW(ty * 4 + i, kk)];
        float4 b4 = *reinterpret_cast<const float4*>(&B2[kk * DD + tx * 4]);
        float b[4] = {b4.x, b4.y, b4.z, b4.w};
        #pragma unroll
        for (int i = 0; i < 4; i++)
            #pragma unroll
            for (int j = 0; j < 4; j++) out[i][j] = fmaf(a[i], b[j], out[i][j]);
    }
    __syncthreads();

    // Store prefetched KV into B2; out += q @ KV
    #pragma unroll
    for (int r = 0; r < 4; r++)
        *reinterpret_cast<float4*>(&B2[tid * 4 + r * 1024]) = kvp[r];
    __syncthreads();
    for (int kk = 0; kk < DD; kk++) {
        float a[4];
        #pragma unroll
        for (int i = 0; i < 4; i++) a[i] = QT[SW(kk, ty * 4 + i)];
        float4 b4 = *reinterpret_cast<const float4*>(&B2[kk * DD + tx * 4]);
        float b[4] = {b4.x, b4.y, b4.z, b4.w};
        #pragma unroll
        for (int i = 0; i < 4; i++)
            #pragma unroll
            for (int j = 0; j < 4; j++) out[i][j] = fmaf(a[i], b[j], out[i][j]);
    }

    // Store to attn in [B,N,H,D] = [B,N,C] layout for the final GEMM.
    const int b = bh >> 3, h = bh & 7;
    #pragma unroll
    for (int i = 0; i < 4; i++) {
        const int tg = c * LCH + ty * 4 + i;
        const size_t rb = ((size_t)b * NN + tg) * CC + h * DD;
        float4 o = {out[i][0], out[i][1], out[i][2], out[i][3]};
        *reinterpret_cast<float4*>(&g_attn[rb + tx * 4]) = o;
    }
}

// ---------------------------------------------------------------------------
extern "C" void kernel_launch(void* const* d_in, const int* in_sizes, int n_in,
                              void* d_out, int out_size) {
    const float* x      = (const float*)d_in[0];
    const float* W_qkv  = (const float*)d_in[1];
    const float* W_proj = (const float*)d_in[2];
    const float* b_proj = (const float*)d_in[3];
    float* out = (float*)d_out;

    gemm_nt_kernel<0><<<dim3(MM / 128, K3C / 128), 256>>>(x, W_qkv, nullptr, nullptr);
    chunk_kv_kernel<<<BHH * NCH, 256>>>();
    scan_kernel<<<256, 256>>>();   // 65536 threads: one per (bh, elem) sequence
    attn_chunk_kernel<<<BHH * NCH, 256>>>();
    gemm_nt_kernel<1><<<dim3(MM / 128, CC / 128), 256>>>(nullptr, W_proj, b_proj, out);
}

// round 17
// speedup vs baseline: 1.6882x; 1.6882x over previous
#include <cuda_runtime.h>
#include <cuda_bf16.h>
#include <math.h>
#include <stdint.h>

// Problem constants
#define BB   2
#define NN   8192
#define CC   512
#define HH   8
#define DD   64
#define MM   (BB*NN)      // 16384 rows
#define K3C  (3*CC)       // 1536
#define LCH  64           // chunk length
#define NCH  (NN/LCH)     // 128 chunks per (b,h)
#define BHH  (BB*HH)      // 16

// Scratch (device globals; no allocation allowed)
__device__ float g_q[BHH*NN*DD];
__device__ float g_k[BHH*NN*DD];
__device__ float g_v[BHH*NN*DD];
__device__ float g_S[BHH*NCH*DD*DD];
__device__ float g_attn[BB*NN*CC];

// Split-precision bf16 operands for tensor-core GEMMs
__device__ __nv_bfloat16 gx_hi[MM*CC],  gx_lo[MM*CC];
__device__ __nv_bfloat16 gwq_hi[K3C*CC], gwq_lo[K3C*CC];
__device__ __nv_bfloat16 gwp_hi[CC*CC],  gwp_lo[CC*CC];
__device__ __nv_bfloat16 gat_hi[MM*CC],  gat_lo[MM*CC];

__device__ __forceinline__ float feat(float x) {
    return x > 0.f ? x + 1.f : __expf(x);
}

__device__ __forceinline__ uint32_t smem_u32(const void* p) {
    uint32_t a;
    asm("{ .reg .u64 t; cvta.to.shared.u64 t, %1; cvt.u32.u64 %0, t; }" : "=r"(a) : "l"(p));
    return a;
}

// ldmatrix x4: four 8x8 b16 tiles; lanes 0-7 address tile0 rows, 8-15 tile1, ...
__device__ __forceinline__ void ldm_x4(uint32_t* r, uint32_t addr) {
    asm volatile("ldmatrix.sync.aligned.m8n8.x4.shared.b16 {%0,%1,%2,%3}, [%4];"
                 : "=r"(r[0]), "=r"(r[1]), "=r"(r[2]), "=r"(r[3]) : "r"(addr));
}

// mma m16n8k16 row.col bf16 -> fp32, accumulate in place
__device__ __forceinline__ void mma16816(float* d, const uint32_t* a, const uint32_t* b) {
    asm volatile(
        "mma.sync.aligned.m16n8k16.row.col.f32.bf16.bf16.f32 "
        "{%0,%1,%2,%3}, {%4,%5,%6,%7}, {%8,%9}, {%0,%1,%2,%3};"
        : "+f"(d[0]), "+f"(d[1]), "+f"(d[2]), "+f"(d[3])
        : "r"(a[0]), "r"(a[1]), "r"(a[2]), "r"(a[3]), "r"(b[0]), "r"(b[1]));
}

// Swizzled byte offset inside a [128 rows][32 bytes] tile buffer:
// chunk position = c ^ ((r>>2)&1)  -> conflict-free ldmatrix reads & stores.
__device__ __forceinline__ uint32_t sw_off(int r, int c) {
    return (uint32_t)(r * 32 + ((c ^ ((r >> 2) & 1)) << 4));
}

// ---------------------------------------------------------------------------
// fp32 -> (bf16 hi, bf16 lo) split conversion. Grid covers n/4 exactly.
// DST: 0=gx (src=x), 1=gwq (src=W_qkv), 2=gwp (src=W_proj), 3=gat (src=g_attn)
// ---------------------------------------------------------------------------
template <int DST>
__global__ __launch_bounds__(256) void cvt_kernel(const float* __restrict__ src) {
    __nv_bfloat16* hi = (DST == 0) ? gx_hi : (DST == 1) ? gwq_hi : (DST == 2) ? gwp_hi : gat_hi;
    __nv_bfloat16* lo = (DST == 0) ? gx_lo : (DST == 1) ? gwq_lo : (DST == 2) ? gwp_lo : gat_lo;
    const float* s = (DST == 3) ? (const float*)g_attn : src;
    const size_t i = ((size_t)blockIdx.x * 256 + threadIdx.x) * 4;
    float4 v = *reinterpret_cast<const float4*>(&s[i]);
    union { __nv_bfloat16 b[4]; uint2 u; } H, L;
    H.b[0] = __float2bfloat16(v.x); L.b[0] = __float2bfloat16(v.x - __bfloat162float(H.b[0]));
    H.b[1] = __float2bfloat16(v.y); L.b[1] = __float2bfloat16(v.y - __bfloat162float(H.b[1]));
    H.b[2] = __float2bfloat16(v.z); L.b[2] = __float2bfloat16(v.z - __bfloat162float(H.b[2]));
    H.b[3] = __float2bfloat16(v.w); L.b[3] = __float2bfloat16(v.w - __bfloat162float(H.b[3]));
    *reinterpret_cast<uint2*>(&hi[i]) = H.u;
    *reinterpret_cast<uint2*>(&lo[i]) = L.u;
}

// ---------------------------------------------------------------------------
// Tensor-core NT GEMM via mma.sync (baseline PTX; runs as HMMA on sm_103):
// Y[M,N] = A[M,512] @ B[N,512]^T with split-bf16 (AhBh + AhBl + AlBh),
// fp32 accumulators. CTA tile 128x128, 8 warps (4x2), warp tile 32x64,
// K-chunk 16, double-buffered swizzled smem.
// MODE 0: A=gx, B=gwq, scatter to g_q/g_k/g_v with feature map.
// MODE 1: A=gat, B=gwp, add bias, write out.
// ---------------------------------------------------------------------------
template <int MODE>
__global__ __launch_bounds__(256) void gemm_mma_kernel(const float* __restrict__ bias,
                                                       float* __restrict__ out) {
    // [stage][array: 0=Ah 1=Al 2=Bh 3=Bl][4096 bytes = 128 rows x 32B]
    __shared__ __align__(16) uint8_t sm[2][4][4096];

    const __nv_bfloat16* Ah = (MODE == 0) ? gx_hi : gat_hi;
    const __nv_bfloat16* Al = (MODE == 0) ? gx_lo : gat_lo;
    const __nv_bfloat16* Bh = (MODE == 0) ? gwq_hi : gwp_hi;
    const __nv_bfloat16* Bl = (MODE == 0) ? gwq_lo : gwp_lo;

    const int m0 = blockIdx.x * 128;
    const int n0 = blockIdx.y * 128;
    const int tid = threadIdx.x;
    const int lane = tid & 31;
    const int wid = tid >> 5;
    const int warp_m = wid & 3;        // 0..3 -> 32-row slices
    const int warp_n = wid >> 2;       // 0..1 -> 64-col slices

    // Gmem load coords: each thread loads one 16B chunk per array per k-chunk.
    const int lrow = tid >> 1;         // 0..127
    const int lchk = tid & 1;          // 0..1 (k-halves of 8 bf16)
    const uint32_t soff = sw_off(lrow, lchk);
    const size_t a_base = (size_t)(m0 + lrow) * CC + lchk * 8;
    const size_t b_base = (size_t)(n0 + lrow) * CC + lchk * 8;

    float acc[2][8][4];
    #pragma unroll
    for (int im = 0; im < 2; im++)
        #pragma unroll
        for (int in = 0; in < 8; in++)
            #pragma unroll
            for (int q = 0; q < 4; q++) acc[im][in][q] = 0.f;

    // Preload chunk 0 into stage 0
    {
        uint4 v0 = *(const uint4*)&Ah[a_base];
        uint4 v1 = *(const uint4*)&Al[a_base];
        uint4 v2 = *(const uint4*)&Bh[b_base];
        uint4 v3 = *(const uint4*)&Bl[b_base];
        *(uint4*)&sm[0][0][soff] = v0;
        *(uint4*)&sm[0][1][soff] = v1;
        *(uint4*)&sm[0][2][soff] = v2;
        *(uint4*)&sm[0][3][soff] = v3;
    }
    __syncthreads();

    // ldmatrix lane addressing
    const int quad = lane >> 3, li = lane & 7;
    // A: quad0 mh0/k0, quad1 mh1/k0, quad2 mh0/k1, quad3 mh1/k1
    const int a_r_local = li + (quad & 1) * 8;     // within 16-row tile
    const int a_khalf = quad >> 1;
    // B: quad0 ntile0/k0, quad1 ntile0/k1, quad2 ntile1/k0, quad3 ntile1/k1
    const int b_r_local = (quad >> 1) * 8 + li;    // within 16-row pair
    const int b_khalf = quad & 1;

    const uint32_t smb = smem_u32(&sm[0][0][0]);
    const uint32_t stage_stride = 4 * 4096;

    #pragma unroll 1
    for (int kc = 0; kc < 32; kc++) {
        uint4 v0, v1, v2, v3;
        if (kc < 31) {
            const size_t off = (size_t)(kc + 1) * 16;
            v0 = *(const uint4*)&Ah[a_base + off];
            v1 = *(const uint4*)&Al[a_base + off];
            v2 = *(const uint4*)&Bh[b_base + off];
            v3 = *(const uint4*)&Bl[b_base + off];
        }

        const uint32_t sbase = smb + (uint32_t)(kc & 1) * stage_stride;

        // A fragments: 2 m-tiles x (hi, lo)
        uint32_t afh[2][4], afl[2][4];
        #pragma unroll
        for (int im = 0; im < 2; im++) {
            const int r = warp_m * 32 + im * 16 + a_r_local;
            const uint32_t o = sw_off(r, a_khalf);
            ldm_x4(afh[im], sbase + 0 * 4096 + o);
            ldm_x4(afl[im], sbase + 1 * 4096 + o);
        }

        // B pairs: 4 pairs of n-tiles; 3 products accumulate
        #pragma unroll
        for (int p = 0; p < 4; p++) {
            const int r = warp_n * 64 + p * 16 + b_r_local;
            const uint32_t o = sw_off(r, b_khalf);
            uint32_t bfh[4], bfl[4];
            ldm_x4(bfh, sbase + 2 * 4096 + o);
            ldm_x4(bfl, sbase + 3 * 4096 + o);
            #pragma unroll
            for (int im = 0; im < 2; im++) {
                mma16816(acc[im][p * 2],     afh[im], &bfh[0]);
                mma16816(acc[im][p * 2],     afh[im], &bfl[0]);
                mma16816(acc[im][p * 2],     afl[im], &bfh[0]);
                mma16816(acc[im][p * 2 + 1], afh[im], &bfh[2]);
                mma16816(acc[im][p * 2 + 1], afh[im], &bfl[2]);
                mma16816(acc[im][p * 2 + 1], afl[im], &bfh[2]);
            }
        }

        if (kc < 31) {
            uint8_t* dst = &sm[(kc + 1) & 1][0][0];
            *(uint4*)(dst + 0 * 4096 + soff) = v0;
            *(uint4*)(dst + 1 * 4096 + soff) = v1;
            *(uint4*)(dst + 2 * 4096 + soff) = v2;
            *(uint4*)(dst + 3 * 4096 + soff) = v3;
            __syncthreads();
        }
    }

    // Epilogue: c-frag mapping: c0,c1 -> (g, tc*2 / +1); c2,c3 -> (g+8, ...)
    const int g = lane >> 2, tc = lane & 3;
    #pragma unroll
    for (int im = 0; im < 2; im++) {
        const int mr0 = m0 + warp_m * 32 + im * 16 + g;
        #pragma unroll
        for (int in = 0; in < 8; in++) {
            const int n = n0 + warp_n * 64 + in * 8 + tc * 2;
            if (MODE == 1) {
                const float b0 = bias[n], b1 = bias[n + 1];
                float2 o0 = {acc[im][in][0] + b0, acc[im][in][1] + b1};
                float2 o1 = {acc[im][in][2] + b0, acc[im][in][3] + b1};
                *reinterpret_cast<float2*>(&out[(size_t)mr0 * CC + n]) = o0;
                *reinterpret_cast<float2*>(&out[(size_t)(mr0 + 8) * CC + n]) = o1;
            } else {
                const int sec = n >> 9;           // constant within the 8-wide n-tile
                const int h = (n >> 6) & 7;
                const int d = n & 63;
                float* dst = (sec == 0) ? g_q : ((sec == 1) ? g_k : g_v);
                float v0 = acc[im][in][0], v1 = acc[im][in][1];
                float v2 = acc[im][in][2], v3 = acc[im][in][3];
                if (sec < 2) { v0 = feat(v0); v1 = feat(v1); v2 = feat(v2); v3 = feat(v3); }
                const int b0i = mr0 >> 13, t0 = mr0 & (NN - 1);
                const int b1i = (mr0 + 8) >> 13, t1 = (mr0 + 8) & (NN - 1);
                float2 o0 = {v0, v1}, o1 = {v2, v3};
                *reinterpret_cast<float2*>(
                    &dst[(((size_t)(b0i * HH + h)) * NN + t0) * DD + d]) = o0;
                *reinterpret_cast<float2*>(
                    &dst[(((size_t)(b1i * HH + h)) * NN + t1) * DD + d]) = o1;
            }
        }
    }
}

// ---------------------------------------------------------------------------
// Kernel 2: per-chunk S_c = k_c^T v_c  (D x D), 2048 blocks of 256 threads.
// ---------------------------------------------------------------------------
__global__ __launch_bounds__(256) void chunk_kv_kernel() {
    const int bh = blockIdx.x >> 7;
    const int c  = blockIdx.x & (NCH - 1);
    __shared__ float Ks[LCH * DD];
    __shared__ float Vs[LCH * DD];
    const size_t cb = ((size_t)bh * NN + (size_t)c * LCH) * DD;
    const int tid = threadIdx.x;
    for (int i = tid * 4; i < LCH * DD; i += 1024) {
        *reinterpret_cast<float4*>(&Ks[i]) = *reinterpret_cast<const float4*>(&g_k[cb + i]);
        *reinterpret_cast<float4*>(&Vs[i]) = *reinterpret_cast<const float4*>(&g_v[cb + i]);
    }
    __syncthreads();
    const int tx = tid & 15, ty = tid >> 4;
    float acc[4][4];
    #pragma unroll
    for (int i = 0; i < 4; i++)
        #pragma unroll
        for (int j = 0; j < 4; j++) acc[i][j] = 0.f;
    for (int t = 0; t < LCH; t++) {
        float4 a4 = *reinterpret_cast<const float4*>(&Ks[t * DD + ty * 4]);
        float4 b4 = *reinterpret_cast<const float4*>(&Vs[t * DD + tx * 4]);
        float a[4] = {a4.x, a4.y, a4.z, a4.w};
        float b[4] = {b4.x, b4.y, b4.z, b4.w};
        #pragma unroll
        for (int i = 0; i < 4; i++)
            #pragma unroll
            for (int j = 0; j < 4; j++) acc[i][j] = fmaf(a[i], b[j], acc[i][j]);
    }
    float* Sb = g_S + (size_t)blockIdx.x * (DD * DD);
    #pragma unroll
    for (int i = 0; i < 4; i++) {
        float4 o = {acc[i][0], acc[i][1], acc[i][2], acc[i][3]};
        *reinterpret_cast<float4*>(&Sb[(ty * 4 + i) * DD + tx * 4]) = o;
    }
}

// ---------------------------------------------------------------------------
// Kernel 3: exclusive prefix sum over chunks. One thread per sequence.
// ---------------------------------------------------------------------------
__global__ __launch_bounds__(256) void scan_kernel() {
    const int g = blockIdx.x * 256 + threadIdx.x;
    const int bh = g >> 12;
    const int elem = g & 4095;
    float* p = g_S + (size_t)bh * NCH * (DD * DD) + elem;
    float run = 0.f;
    #pragma unroll 8
    for (int c = 0; c < NCH; c++) {
        const float s = p[(size_t)c * (DD * DD)];
        p[(size_t)c * (DD * DD)] = run;
        run += s;
    }
}

// ---------------------------------------------------------------------------
// Kernel 4: per chunk  out = tril(q k^T) v + q @ KV_prev.
// ---------------------------------------------------------------------------
#define SW(r, c) (((r) << 6) | ((c) ^ ((r) & 31)))

__global__ __launch_bounds__(256) void attn_chunk_kernel() {
    const int bh = blockIdx.x >> 7;
    const int c  = blockIdx.x & (NCH - 1);
    __shared__ float QT[LCH * DD];
    __shared__ float B1[LCH * DD];
    __shared__ float B2[LCH * DD];
    const size_t cb = ((size_t)bh * NN + (size_t)c * LCH) * DD;
    const int tid = threadIdx.x;
    const int tx = tid & 15, ty = tid >> 4;

    for (int i = tid * 4; i < LCH * DD; i += 1024)
        *reinterpret_cast<float4*>(&B2[i]) = *reinterpret_cast<const float4*>(&g_v[cb + i]);

    for (int i = tid; i < LCH * DD; i += 256) {
        const int t = i >> 6, d = i & 63;
        const float qv = g_q[cb + i];
        const float kv = g_k[cb + i];
        QT[SW(d, t)] = qv;
        B1[SW(d, t)] = kv;
    }
    __syncthreads();

    float A[4][4];
    #pragma unroll
    for (int i = 0; i < 4; i++)
        #pragma unroll
        for (int j = 0; j < 4; j++) A[i][j] = 0.f;
    for (int kk = 0; kk < DD; kk++) {
        float a[4], b[4];
        #pragma unroll
        for (int i = 0; i < 4; i++) a[i] = QT[SW(kk, ty * 4 + i)];
        #pragma unroll
        for (int j = 0; j < 4; j++) b[j] = B1[SW(kk, tx * 4 + j)];
        #pragma unroll
        for (int i = 0; i < 4; i++)
            #pragma unroll
            for (int j = 0; j < 4; j++) A[i][j] = fmaf(a[i], b[j], A[i][j]);
    }
    __syncthreads();

    #pragma unroll
    for (int i = 0; i < 4; i++) {
        const int t = ty * 4 + i;
        #pragma unroll
        for (int j = 0; j < 4; j++) {
            const int s = tx * 4 + j;
            B1[SW(t, s)] = (s <= t) ? A[i][j] : 0.f;
        }
    }
    __syncthreads();

    float4 kvp[4];
    {
        const float* Sb = g_S + (size_t)blockIdx.x * (DD * DD);
        #pragma unroll
        for (int r = 0; r < 4; r++)
            kvp[r] = *reinterpret_cast<const float4*>(&Sb[tid * 4 + r * 1024]);
    }

    float out[4][4];
    #pragma unroll
    for (int i = 0; i < 4; i++)
        #pragma unroll
        for (int j = 0; j < 4; j++) out[i][j] = 0.f;
    for (int kk = 0; kk < LCH; kk++) {
        float a[4];
        #pragma unroll
        for (int i = 0; i < 4; i++) a[i] = B1[SW(ty * 4 + i, kk)];
        float4 b4 = *reinterpret_cast<const float4*>(&B2[kk * DD + tx * 4]);
        float b[4] = {b4.x, b4.y, b4.z, b4.w};
        #pragma unroll
        for (int i = 0; i < 4; i++)
            #pragma unroll
            for (int j = 0; j < 4; j++) out[i][j] = fmaf(a[i], b[j], out[i][j]);
    }
    __syncthreads();

    #pragma unroll
    for (int r = 0; r < 4; r++)
        *reinterpret_cast<float4*>(&B2[tid * 4 + r * 1024]) = kvp[r];
    __syncthreads();
    for (int kk = 0; kk < DD; kk++) {
        float a[4];
        #pragma unroll
        for (int i = 0; i < 4; i++) a[i] = QT[SW(kk, ty * 4 + i)];
        float4 b4 = *reinterpret_cast<const float4*>(&B2[kk * DD + tx * 4]);
        float b[4] = {b4.x, b4.y, b4.z, b4.w};
        #pragma unroll
        for (int i = 0; i < 4; i++)
            #pragma unroll
            for (int j = 0; j < 4; j++) out[i][j] = fmaf(a[i], b[j], out[i][j]);
    }

    const int b = bh >> 3, h = bh & 7;
    #pragma unroll
    for (int i = 0; i < 4; i++) {
        const int tg = c * LCH + ty * 4 + i;
        const size_t rb = ((size_t)b * NN + tg) * CC + h * DD;
        float4 o = {out[i][0], out[i][1], out[i][2], out[i][3]};
        *reinterpret_cast<float4*>(&g_attn[rb + tx * 4]) = o;
    }
}

// ---------------------------------------------------------------------------
extern "C" void kernel_launch(void* const* d_in, const int* in_sizes, int n_in,
                              void* d_out, int out_size) {
    const float* x      = (const float*)d_in[0];
    const float* W_qkv  = (const float*)d_in[1];
    const float* W_proj = (const float*)d_in[2];
    const float* b_proj = (const float*)d_in[3];
    float* out = (float*)d_out;

    cvt_kernel<0><<<MM * CC / 1024, 256>>>(x);
    cvt_kernel<1><<<K3C * CC / 1024, 256>>>(W_qkv);
    cvt_kernel<2><<<CC * CC / 1024, 256>>>(W_proj);

    gemm_mma_kernel<0><<<dim3(MM / 128, K3C / 128), 256>>>(nullptr, nullptr);
    chunk_kv_kernel<<<BHH * NCH, 256>>>();
    scan_kernel<<<256, 256>>>();
    attn_chunk_kernel<<<BHH * NCH, 256>>>();
    cvt_kernel<3><<<MM * CC / 1024, 256>>>(nullptr);
    gemm_mma_kernel<1><<<dim3(MM / 128, CC / 128), 256>>>(b_proj, out);
}